// round 15
// baseline (speedup 1.0000x reference)
#include <cuda_runtime.h>
#include <cuda_fp16.h>
#include <math.h>
#include <stdint.h>

#define SEQ   512
#define BATCH 64
#define INP   64
#define HID   1024
#define G4    (4 * HID)
#define NBLK  128
#define NTHR  256

// ---- static scratch ----
__device__ float g_xg[(size_t)SEQ * BATCH * G4];     // [bx][t*32+bl][64]
__device__ half  g_h_hi[(size_t)SEQ * BATCH * HID];  // frag layout [t][mt][kt][lane]x8
__device__ half  g_w_hi[(size_t)G4 * HID];
__device__ half  g_w_lo[(size_t)G4 * HID];
__device__ half  g_x_hi[(size_t)SEQ * BATCH * INP];
__device__ half  g_x_lo[(size_t)SEQ * BATCH * INP];
__device__ unsigned g_flags[NBLK * 8];   // padded 32B; zero at rest
__device__ unsigned g_done;

// ---- helpers ----
__device__ __forceinline__ void mma16816(float c[4], const uint32_t* a, const uint32_t* b) {
    asm volatile("mma.sync.aligned.m16n8k16.row.col.f32.f16.f16.f32 "
        "{%0,%1,%2,%3}, {%4,%5,%6,%7}, {%8,%9}, {%0,%1,%2,%3};\n"
        : "+f"(c[0]), "+f"(c[1]), "+f"(c[2]), "+f"(c[3])
        : "r"(a[0]), "r"(a[1]), "r"(a[2]), "r"(a[3]), "r"(b[0]), "r"(b[1]));
}
__device__ __forceinline__ void ldsm4(uint32_t r[4], const half* p) {
    uint32_t a = (uint32_t)__cvta_generic_to_shared(p);
    asm volatile("ldmatrix.sync.aligned.m8n8.x4.shared.b16 {%0,%1,%2,%3}, [%4];\n"
        : "=r"(r[0]), "=r"(r[1]), "=r"(r[2]), "=r"(r[3]) : "r"(a));
}
__device__ __forceinline__ void ldsm2(uint32_t r[2], const half* p) {
    uint32_t a = (uint32_t)__cvta_generic_to_shared(p);
    asm volatile("ldmatrix.sync.aligned.m8n8.x2.shared.b16 {%0,%1}, [%2];\n"
        : "=r"(r[0]), "=r"(r[1]) : "r"(a));
}
__device__ __forceinline__ void cp16(void* dst, const void* src) {
    uint32_t d = (uint32_t)__cvta_generic_to_shared(dst);
    asm volatile("cp.async.cg.shared.global [%0], [%1], 16;\n" :: "r"(d), "l"(src));
}
#define CP_COMMIT() asm volatile("cp.async.commit_group;\n")
#define CP_WAIT0()  asm volatile("cp.async.wait_group 0;\n")

__device__ __forceinline__ void cpbulk(void* dst, const void* src, unsigned bytes, void* mbar) {
    uint32_t d = (uint32_t)__cvta_generic_to_shared(dst);
    uint32_t m = (uint32_t)__cvta_generic_to_shared(mbar);
    asm volatile("cp.async.bulk.shared::cta.global.mbarrier::complete_tx::bytes "
                 "[%0], [%1], %2, [%3];\n" :: "r"(d), "l"(src), "r"(bytes), "r"(m) : "memory");
}
__device__ __forceinline__ void mbar_init(void* mbar, unsigned cnt) {
    uint32_t m = (uint32_t)__cvta_generic_to_shared(mbar);
    asm volatile("mbarrier.init.shared.b64 [%0], %1;" :: "r"(m), "r"(cnt) : "memory");
}
__device__ __forceinline__ void mbar_inval(void* mbar) {
    uint32_t m = (uint32_t)__cvta_generic_to_shared(mbar);
    asm volatile("mbarrier.inval.shared.b64 [%0];" :: "r"(m) : "memory");
}
__device__ __forceinline__ void mbar_expect(void* mbar, unsigned bytes) {
    uint32_t m = (uint32_t)__cvta_generic_to_shared(mbar);
    asm volatile("mbarrier.arrive.expect_tx.shared.b64 _, [%0], %1;"
                 :: "r"(m), "r"(bytes) : "memory");
}
__device__ __forceinline__ void mbar_wait(void* mbar, unsigned parity) {
    uint32_t m = (uint32_t)__cvta_generic_to_shared(mbar);
    asm volatile(
        "{\n.reg .pred P;\n"
        "W%=: mbarrier.try_wait.parity.acquire.cta.shared::cta.b64 P, [%0], %1, 0x989680;\n"
        "@P bra D%=;\n"
        "bra W%=;\n"
        "D%=: }\n" :: "r"(m), "r"(parity) : "memory");
}
__device__ __forceinline__ unsigned ld_acq(const unsigned* p) {
    unsigned v;
    asm volatile("ld.acquire.gpu.u32 %0, [%1];" : "=r"(v) : "l"(p) : "memory");
    return v;
}
__device__ __forceinline__ void st_rel(unsigned* p, unsigned v) {
    asm volatile("st.release.gpu.u32 [%0], %1;" :: "l"(p), "r"(v) : "memory");
}
__device__ __forceinline__ float tanh_fast(float x) {
    float y;
    asm("tanh.approx.f32 %0, %1;" : "=f"(y) : "f"(x));
    return y;
}
__device__ __forceinline__ float sigmoid_fast(float x) {
    return 0.5f * tanh_fast(0.5f * x) + 0.5f;
}

// Single-hop grid barrier (proven in R9/R11/R13); monotonic targets.
__device__ __forceinline__ void grid_barrier(unsigned target) {
    __syncthreads();
    int tid = threadIdx.x;
    if (tid == 0) st_rel(&g_flags[blockIdx.x * 8], target);
    if (tid < NBLK) {
        while (ld_acq(&g_flags[tid * 8]) < target) { }
    }
    __syncthreads();
}

__global__ void split_fp16_kernel(const float* __restrict__ src,
                                  half* __restrict__ hi, half* __restrict__ lo, int n) {
    int i4 = (blockIdx.x * 256 + threadIdx.x) * 4;
    if (i4 >= n) return;
    float4 v = *(const float4*)(src + i4);
    half h0 = __float2half(v.x), h1 = __float2half(v.y);
    half h2 = __float2half(v.z), h3 = __float2half(v.w);
    hi[i4+0]=h0; hi[i4+1]=h1; hi[i4+2]=h2; hi[i4+3]=h3;
    lo[i4+0]=__float2half(v.x-__half2float(h0));
    lo[i4+1]=__float2half(v.y-__half2float(h1));
    lo[i4+2]=__float2half(v.z-__half2float(h2));
    lo[i4+3]=__float2half(v.w-__half2float(h3));
}

// ---------------------------------------------------------------------------
// xg scatter target: block bx = bh*64+jg owns [t][bl 32][n 64] (n = g*16+jl)
// ---------------------------------------------------------------------------
__global__ void __launch_bounds__(256)
hgemm_split_kernel(const half* __restrict__ Ahi, const half* __restrict__ Alo,
                   const half* __restrict__ Whi, const half* __restrict__ Wlo,
                   const float* __restrict__ b1, const float* __restrict__ b2,
                   float* __restrict__ C, int M, int K, int achunked) {
    __shared__ half sA[2][2][64 * 40];
    __shared__ half sB[2][2][64 * 40];
    const int tid = threadIdx.x, lane = tid & 31, w = tid >> 5;
    const int mi = w & 1, ni = w >> 1;
    const int r = lane >> 2, q = lane & 3;
    const int m0 = blockIdx.y * 64, n0 = blockIdx.x * 64;
    const int srow = tid >> 2, skq = (tid & 3) * 8;

    float acc[2][2][4];
#pragma unroll
    for (int a = 0; a < 2; a++)
#pragma unroll
        for (int b = 0; b < 2; b++)
#pragma unroll
            for (int c = 0; c < 4; c++) acc[a][b][c] = 0.f;

    const int NIT = K / 32;
    const half* fragB = Ahi + (size_t)(m0 >> 6) * 65536 + lane * 8;

    uint32_t Ac[2][2][4];
    if (achunked) {
#pragma unroll
        for (int s = 0; s < 2; s++)
#pragma unroll
            for (int mtl = 0; mtl < 2; mtl++) {
                uint4 v = *(const uint4*)(fragB + (((mi*2+mtl)*64 + s) * 256));
                Ac[s][mtl][0]=v.x; Ac[s][mtl][1]=v.y; Ac[s][mtl][2]=v.z; Ac[s][mtl][3]=v.w;
            }
    } else {
        cp16(&sA[0][0][srow*40+skq], Ahi + (size_t)(m0+srow)*K + skq);
        cp16(&sA[0][1][srow*40+skq], Alo + (size_t)(m0+srow)*K + skq);
    }
    cp16(&sB[0][0][srow*40+skq], Whi + (size_t)(n0+srow)*K + skq);
    cp16(&sB[0][1][srow*40+skq], Wlo + (size_t)(n0+srow)*K + skq);
    CP_COMMIT();

    for (int it = 0; it < NIT; it++) {
        CP_WAIT0();
        __syncthreads();
        uint32_t An[2][2][4];
        if (it + 1 < NIT) {
            int k0 = (it+1)*32, bf = (it+1) & 1;
            if (achunked) {
#pragma unroll
                for (int s = 0; s < 2; s++)
#pragma unroll
                    for (int mtl = 0; mtl < 2; mtl++) {
                        uint4 v = *(const uint4*)(fragB + (((mi*2+mtl)*64 + (it+1)*2 + s) * 256));
                        An[s][mtl][0]=v.x; An[s][mtl][1]=v.y; An[s][mtl][2]=v.z; An[s][mtl][3]=v.w;
                    }
            } else {
                cp16(&sA[bf][0][srow*40+skq], Ahi + (size_t)(m0+srow)*K + k0 + skq);
                cp16(&sA[bf][1][srow*40+skq], Alo + (size_t)(m0+srow)*K + k0 + skq);
            }
            cp16(&sB[bf][0][srow*40+skq], Whi + (size_t)(n0+srow)*K + k0 + skq);
            cp16(&sB[bf][1][srow*40+skq], Wlo + (size_t)(n0+srow)*K + k0 + skq);
            CP_COMMIT();
        }
        const half *Abh = sA[it&1][0], *Abl = sA[it&1][1];
        const half *Bbh = sB[it&1][0], *Bbl = sB[it&1][1];
#pragma unroll
        for (int s = 0; s < 2; s++) {
            const int kb = s * 16;
            uint32_t Ah[2][4], Al[2][4], Bh[2][2], Bl[2][2];
            if (achunked) {
#pragma unroll
                for (int mt = 0; mt < 2; mt++)
#pragma unroll
                    for (int z = 0; z < 4; z++) Ah[mt][z] = Ac[s][mt][z];
            } else {
#pragma unroll
                for (int mt = 0; mt < 2; mt++) {
                    ldsm4(Ah[mt], Abh + (mi*32 + mt*16 + (lane&15))*40 + kb + ((lane>>4)<<3));
                    ldsm4(Al[mt], Abl + (mi*32 + mt*16 + (lane&15))*40 + kb + ((lane>>4)<<3));
                }
            }
#pragma unroll
            for (int nt = 0; nt < 2; nt++) {
                ldsm2(Bh[nt], Bbh + (ni*16 + nt*8 + (lane&7))*40 + kb + (((lane>>3)&1)<<3));
                ldsm2(Bl[nt], Bbl + (ni*16 + nt*8 + (lane&7))*40 + kb + (((lane>>3)&1)<<3));
            }
#pragma unroll
            for (int mt = 0; mt < 2; mt++)
#pragma unroll
                for (int nt = 0; nt < 2; nt++) {
                    mma16816(acc[mt][nt], Ah[mt], Bh[nt]);
                    mma16816(acc[mt][nt], Ah[mt], Bl[nt]);
                    if (!achunked) mma16816(acc[mt][nt], Al[mt], Bh[nt]);
                }
        }
        if (achunked && it + 1 < NIT) {
#pragma unroll
            for (int s = 0; s < 2; s++)
#pragma unroll
                for (int mtl = 0; mtl < 2; mtl++)
#pragma unroll
                    for (int z = 0; z < 4; z++) Ac[s][mtl][z] = An[s][mtl][z];
        }
        __syncthreads();
    }
#pragma unroll
    for (int mt = 0; mt < 2; mt++)
#pragma unroll
        for (int nt = 0; nt < 2; nt++) {
            int row = m0 + mi*32 + mt*16 + r;
            int col = n0 + ni*16 + nt*8 + q*2;
            int g = col >> 10, j = col & 1023;
            int jg = j >> 4, jl = j & 15;
            int b = row & 63, bh = b >> 5, bl = b & 31;
            int bxo = bh * 64 + jg;
            float bs0 = b1[col] + b2[col], bs1 = b1[col+1] + b2[col+1];
            size_t base = (size_t)bxo * ((size_t)SEQ * 32 * 64)
                        + ((size_t)(row >> 6) * 32 + bl) * 64 + g * 16 + jl;
            *(float2*)(C + base) = make_float2(acc[mt][nt][0]+bs0, acc[mt][nt][1]+bs1);
            *(float2*)(C + base + 8*64) = make_float2(acc[mt][nt][2]+bs0, acc[mt][nt][3]+bs1);
        }
}

// ---------------------------------------------------------------------------
// Persistent recurrence: block = (jg 64) x (bh 2): M=32 batch-half,
// N=64 gate rows, K=1024. Warps: mtl = w&1, kq = w>>1.
// A fragments: all 16 segments front-batched into registers (MLP=16).
// ---------------------------------------------------------------------------
#define WSS 1032
#define WS_B      (64 * WSS * 2)            // 132096
#define PS_OFF    WS_B                      // 132096
#define PS_B      (4 * 32 * 66 * 4)         // 33792
#define XG_OFF    (PS_OFF + PS_B)           // 165888
#define MB_OFF    (XG_OFF + 16384)          // 182272
#define SMEM_TOT  (MB_OFF + 16)             // 182288
#define XG_B      8192u

__global__ void __launch_bounds__(NTHR, 1)
lstm_layer_mma(const float* __restrict__ xg,     // [bx][t*32+bl][64] incl. biases
               const float* __restrict__ Whh,    // [4H][H] fp32
               half* __restrict__ hfrag,         // frag layout
               float* __restrict__ hseq)         // [t][b][1024] fp32 or null
{
    extern __shared__ char smem[];
    half*  wsh   = (half*)smem;
    float* psum  = (float*)(smem + PS_OFF);
    float* xgs   = (float*)(smem + XG_OFF);
    uint64_t* xmb = (uint64_t*)(smem + MB_OFF);

    const int tid = threadIdx.x, lane = tid & 31, w = tid >> 5;
    const int mtl = w & 1, kq = w >> 1;
    const int bx = blockIdx.x;
    const int jg = bx & 63, bh = bx >> 6;
    const int j0 = jg * 16;
    const float* xgb = xg + (size_t)bx * ((size_t)SEQ * 32 * 64);

    if (tid == 0) { mbar_init(&xmb[0], 1); mbar_init(&xmb[1], 1); }

    // one-time: Whh slice -> smem fp16 (rows n = g*16 + jl)
    for (int idx = tid; idx < 64 * 256; idx += NTHR) {
        int n = idx >> 8, kq4 = (idx & 255) * 4;
        int grow = (n >> 4) * HID + j0 + (n & 15);
        float4 v = *(const float4*)(Whh + (size_t)grow * HID + kq4);
        half* ph = wsh + n * WSS + kq4;
        ph[0]=__float2half(v.x); ph[1]=__float2half(v.y);
        ph[2]=__float2half(v.z); ph[3]=__float2half(v.w);
    }
    __syncthreads();

    if (tid == 0) {    // prologue: xg(0)
        mbar_expect(&xmb[0], XG_B);
        cpbulk(xgs, xgb, XG_B, &xmb[0]);
    }

    unsigned xph[2] = {0u, 0u};
    const int pq = tid >> 6, psub = (tid >> 5) & 1, pla = tid & 31;
    const int pr = pla >> 2, pcc = (pla & 3) * 2 + psub * 8;
    float creg[4] = {0.f, 0.f, 0.f, 0.f};
    const int lrow = lane & 7, lcol = ((lane >> 3) & 3) * 8;

    for (int t = 0; t < SEQ; t++) {
        if (tid == 0 && t + 1 < SEQ) {
            mbar_expect(&xmb[(t+1)&1], XG_B);
            cpbulk((char*)xgs + ((t+1)&1) * XG_B, xgb + (size_t)(t+1) * 2048, XG_B, &xmb[(t+1)&1]);
        }

        if (t > 0) {
            // A frags: mtile 2bh+mtl, ktiles [kq*16, kq*16+16) — all 16 up front
            const half* hb = hfrag + (size_t)(t-1) * 65536
                             + ((size_t)(2*bh + mtl) * 64 + kq * 16) * 256 + lane * 8;
            uint32_t abuf[16][4];
#pragma unroll
            for (int i = 0; i < 16; i++) {
                uint4 v = *(const uint4*)(hb + i * 256);
                abuf[i][0]=v.x; abuf[i][1]=v.y; abuf[i][2]=v.z; abuf[i][3]=v.w;
            }
            float acc[8][4];
#pragma unroll
            for (int nt = 0; nt < 8; nt++)
#pragma unroll
                for (int c = 0; c < 4; c++) acc[nt][c] = 0.f;

            uint32_t B0[8][4], B1[8][4];
#pragma unroll
            for (int nt = 0; nt < 8; nt++)
                ldsm4(B0[nt], wsh + (nt*8 + lrow)*WSS + kq*256 + lcol);

#pragma unroll
            for (int u = 0; u < 8; u++) {
                uint32_t (*Bc)[4] = (u & 1) ? B1 : B0;
                uint32_t (*Bn)[4] = (u & 1) ? B0 : B1;
                if (u < 7) {
                    const int kg = kq*256 + (u+1)*32;
#pragma unroll
                    for (int nt = 0; nt < 8; nt++)
                        ldsm4(Bn[nt], wsh + (nt*8 + lrow)*WSS + kg + lcol);
                }
#pragma unroll
                for (int nt = 0; nt < 8; nt++) {
                    mma16816(acc[nt], abuf[2*u],   Bc[nt]);
                    mma16816(acc[nt], abuf[2*u+1], Bc[nt]+2);
                }
            }

            // psum[kq][bl 32][n 64+2]
            int prow = mtl*16 + (lane>>2), pcol = (lane&3)*2;
#pragma unroll
            for (int nt = 0; nt < 8; nt++) {
                *(float2*)(psum + (kq*32 + prow)*66 + nt*8 + pcol) =
                    make_float2(acc[nt][0], acc[nt][1]);
                *(float2*)(psum + (kq*32 + prow + 8)*66 + nt*8 + pcol) =
                    make_float2(acc[nt][2], acc[nt][3]);
            }
        }
        __syncthreads();   // psum complete (and prev pointwise done)

        // pointwise: tid<128; elems (bl0,cc),(bl0,cc+1),(bl1,cc),(bl1,cc+1)
        mbar_wait(&xmb[t&1], xph[t&1]); xph[t&1] ^= 1u;
        if (tid < 128) {
            const float* xt = xgs + (t&1) * 2048;
            const int bl0 = pq*16 + pr, bl1 = bl0 + 8;
            float gate[4][4];
#pragma unroll
            for (int g = 0; g < 4; g++) {
                int n = g*16 + pcc;
                float2 x0 = *(const float2*)(xt + bl0*64 + n);
                float2 x1 = *(const float2*)(xt + bl1*64 + n);
                float v0 = x0.x, v1 = x0.y, v2 = x1.x, v3 = x1.y;
                if (t > 0) {
#pragma unroll
                    for (int k = 0; k < 4; k++) {
                        float2 p0 = *(const float2*)(psum + (k*32 + bl0)*66 + n);
                        float2 p1 = *(const float2*)(psum + (k*32 + bl1)*66 + n);
                        v0 += p0.x; v1 += p0.y; v2 += p1.x; v3 += p1.y;
                    }
                }
                gate[g][0] = v0; gate[g][1] = v1; gate[g][2] = v2; gate[g][3] = v3;
            }
            half hh[4];
            float hv[4];
#pragma unroll
            for (int e = 0; e < 4; e++) {
                float ig = sigmoid_fast(gate[0][e]);
                float fg = sigmoid_fast(gate[1][e]);
                float gg = tanh_fast(gate[2][e]);
                float og = sigmoid_fast(gate[3][e]);
                float cn = fmaf(fg, creg[e], ig * gg);
                creg[e] = cn;
                hv[e] = og * tanh_fast(cn);
                hh[e] = __float2half(hv[e]);
            }
            if (hseq) {
                float* h_out = hseq + (size_t)t * BATCH * HID;
                int b0 = bh*32 + bl0, b1v = bh*32 + bl1, j = j0 + pcc;
                *(float2*)(h_out + (size_t)b0 * HID + j) = make_float2(hv[0], hv[1]);
                *(float2*)(h_out + (size_t)b1v * HID + j) = make_float2(hv[2], hv[3]);
            }
            half2 p0 = __halves2half2(hh[0], hh[1]);
            half2 p1 = __halves2half2(hh[2], hh[3]);
            uint2 u2 = make_uint2(*(unsigned*)&p0, *(unsigned*)&p1);
            size_t o = (size_t)t * 65536 + ((size_t)(2*bh + pq) * 64 + jg) * 256
                       + pla * 8 + psub * 4;
            *(uint2*)(hfrag + o) = u2;
        }
        grid_barrier((unsigned)(t + 1));
    }

    // end-of-kernel reset (last block resets flags)
    __syncthreads();
    if (tid == 0) {
        unsigned c = atomicAdd(&g_done, 1u);
        if (c == NBLK - 1u) {
            for (int i = 0; i < NBLK; i++) g_flags[i * 8] = 0u;
            __threadfence();
            g_done = 0u;
        }
        mbar_inval(&xmb[0]); mbar_inval(&xmb[1]);
    }
}

// ---------------------------------------------------------------------------
__global__ void final_linear_kernel(const float* __restrict__ h_last,
                                    const float* __restrict__ Wl,
                                    const float* __restrict__ bl,
                                    float* __restrict__ y) {
    int b = blockIdx.x;
    __shared__ float red[128];
    float s = 0.f;
    for (int k = threadIdx.x; k < HID; k += 128)
        s += h_last[(size_t)b * HID + k] * Wl[k];
    red[threadIdx.x] = s;
    __syncthreads();
    for (int off = 64; off > 0; off >>= 1) {
        if (threadIdx.x < off) red[threadIdx.x] += red[threadIdx.x + off];
        __syncthreads();
    }
    if (threadIdx.x == 0) y[b] = red[0] + bl[0];
}

// ---------------------------------------------------------------------------
extern "C" void kernel_launch(void* const* d_in, const int* in_sizes, int n_in,
                              void* d_out, int out_size) {
    (void)in_sizes; (void)n_in; (void)out_size;
    const float* x    = (const float*)d_in[0];
    const float* Wih0 = (const float*)d_in[1];
    const float* Whh0 = (const float*)d_in[2];
    const float* bih0 = (const float*)d_in[3];
    const float* bhh0 = (const float*)d_in[4];
    const float* Wih1 = (const float*)d_in[5];
    const float* Whh1 = (const float*)d_in[6];
    const float* bih1 = (const float*)d_in[7];
    const float* bhh1 = (const float*)d_in[8];
    const float* Wlin = (const float*)d_in[9];
    const float* blin = (const float*)d_in[10];

    float* out      = (float*)d_out;
    float* lstm_out = out;
    float* ypred    = out + (size_t)SEQ * BATCH * HID;

    float *xg; half *hhi, *whi, *wlo, *xhi, *xlo;
    cudaGetSymbolAddress((void**)&xg,  g_xg);
    cudaGetSymbolAddress((void**)&hhi, g_h_hi);
    cudaGetSymbolAddress((void**)&whi, g_w_hi);
    cudaGetSymbolAddress((void**)&wlo, g_w_lo);
    cudaGetSymbolAddress((void**)&xhi, g_x_hi);
    cudaGetSymbolAddress((void**)&xlo, g_x_lo);

    cudaFuncSetAttribute(lstm_layer_mma,
                         cudaFuncAttributeMaxDynamicSharedMemorySize, SMEM_TOT);

    const int M = SEQ * BATCH;
    dim3 gg(G4 / 64, M / 64);

    // Layer 0
    int nx = SEQ * BATCH * INP;
    split_fp16_kernel<<<nx/4/256, 256>>>(x, xhi, xlo, nx);
    int nw0 = G4 * INP;
    split_fp16_kernel<<<nw0/4/256, 256>>>(Wih0, whi, wlo, nw0);
    hgemm_split_kernel<<<gg, 256>>>(xhi, xlo, whi, wlo, bih0, bhh0, xg, M, INP, 0);
    lstm_layer_mma<<<NBLK, NTHR, SMEM_TOT>>>(xg, Whh0, hhi, (float*)0);

    // Layer 1
    int nw1 = G4 * HID;
    split_fp16_kernel<<<nw1/4/256, 256>>>(Wih1, whi, wlo, nw1);
    hgemm_split_kernel<<<gg, 256>>>(hhi, (const half*)0, whi, wlo, bih1, bhh1, xg, M, HID, 1);
    lstm_layer_mma<<<NBLK, NTHR, SMEM_TOT>>>(xg, Whh1, hhi, lstm_out);

    // Head
    final_linear_kernel<<<BATCH, 128>>>(lstm_out + (size_t)(SEQ-1) * BATCH * HID,
                                        Wlin, blin, ypred);
}

// round 16
// speedup vs baseline: 1.6439x; 1.6439x over previous
#include <cuda_runtime.h>
#include <cuda_fp16.h>
#include <math.h>
#include <stdint.h>

#define SEQ   512
#define BATCH 64
#define INP   64
#define HID   1024
#define G4    (4 * HID)
#define NBLK  128
#define NTHR  256

// ---- static scratch ----
__device__ float g_xg[(size_t)SEQ * BATCH * G4];     // [jb][t*64+b][32] layer-0 xg
__device__ half  g_h1f[(size_t)SEQ * BATCH * HID];   // h1 frag layout [t][mt][kt][lane]x8
__device__ half  g_h2f[(size_t)SEQ * BATCH * HID];   // h2 frag layout
__device__ half  g_w_hi[(size_t)G4 * HID];
__device__ half  g_w_lo[(size_t)G4 * HID];
__device__ half  g_x_hi[(size_t)SEQ * BATCH * INP];
__device__ half  g_x_lo[(size_t)SEQ * BATCH * INP];
__device__ unsigned g_flags[NBLK * 8];   // padded 32B; zero at rest
__device__ unsigned g_done;

// ---- helpers ----
__device__ __forceinline__ void mma16816(float c[4], const uint32_t* a, const uint32_t* b) {
    asm volatile("mma.sync.aligned.m16n8k16.row.col.f32.f16.f16.f32 "
        "{%0,%1,%2,%3}, {%4,%5,%6,%7}, {%8,%9}, {%0,%1,%2,%3};\n"
        : "+f"(c[0]), "+f"(c[1]), "+f"(c[2]), "+f"(c[3])
        : "r"(a[0]), "r"(a[1]), "r"(a[2]), "r"(a[3]), "r"(b[0]), "r"(b[1]));
}
__device__ __forceinline__ void ldsm4(uint32_t r[4], const half* p) {
    uint32_t a = (uint32_t)__cvta_generic_to_shared(p);
    asm volatile("ldmatrix.sync.aligned.m8n8.x4.shared.b16 {%0,%1,%2,%3}, [%4];\n"
        : "=r"(r[0]), "=r"(r[1]), "=r"(r[2]), "=r"(r[3]) : "r"(a));
}
__device__ __forceinline__ void ldsm2(uint32_t r[2], const half* p) {
    uint32_t a = (uint32_t)__cvta_generic_to_shared(p);
    asm volatile("ldmatrix.sync.aligned.m8n8.x2.shared.b16 {%0,%1}, [%2];\n"
        : "=r"(r[0]), "=r"(r[1]) : "r"(a));
}
__device__ __forceinline__ void cp16(void* dst, const void* src) {
    uint32_t d = (uint32_t)__cvta_generic_to_shared(dst);
    asm volatile("cp.async.cg.shared.global [%0], [%1], 16;\n" :: "r"(d), "l"(src));
}
#define CP_COMMIT() asm volatile("cp.async.commit_group;\n")
#define CP_WAIT0()  asm volatile("cp.async.wait_group 0;\n")

__device__ __forceinline__ void cpbulk(void* dst, const void* src, unsigned bytes, void* mbar) {
    uint32_t d = (uint32_t)__cvta_generic_to_shared(dst);
    uint32_t m = (uint32_t)__cvta_generic_to_shared(mbar);
    asm volatile("cp.async.bulk.shared::cta.global.mbarrier::complete_tx::bytes "
                 "[%0], [%1], %2, [%3];\n" :: "r"(d), "l"(src), "r"(bytes), "r"(m) : "memory");
}
__device__ __forceinline__ void mbar_init(void* mbar, unsigned cnt) {
    uint32_t m = (uint32_t)__cvta_generic_to_shared(mbar);
    asm volatile("mbarrier.init.shared.b64 [%0], %1;" :: "r"(m), "r"(cnt) : "memory");
}
__device__ __forceinline__ void mbar_inval(void* mbar) {
    uint32_t m = (uint32_t)__cvta_generic_to_shared(mbar);
    asm volatile("mbarrier.inval.shared.b64 [%0];" :: "r"(m) : "memory");
}
__device__ __forceinline__ void mbar_expect(void* mbar, unsigned bytes) {
    uint32_t m = (uint32_t)__cvta_generic_to_shared(mbar);
    asm volatile("mbarrier.arrive.expect_tx.shared.b64 _, [%0], %1;"
                 :: "r"(m), "r"(bytes) : "memory");
}
__device__ __forceinline__ void mbar_wait(void* mbar, unsigned parity) {
    uint32_t m = (uint32_t)__cvta_generic_to_shared(mbar);
    asm volatile(
        "{\n.reg .pred P;\n"
        "W%=: mbarrier.try_wait.parity.acquire.cta.shared::cta.b64 P, [%0], %1, 0x989680;\n"
        "@P bra D%=;\n"
        "bra W%=;\n"
        "D%=: }\n" :: "r"(m), "r"(parity) : "memory");
}
__device__ __forceinline__ unsigned ld_acq(const unsigned* p) {
    unsigned v;
    asm volatile("ld.acquire.gpu.u32 %0, [%1];" : "=r"(v) : "l"(p) : "memory");
    return v;
}
__device__ __forceinline__ void st_rel(unsigned* p, unsigned v) {
    asm volatile("st.release.gpu.u32 [%0], %1;" :: "l"(p), "r"(v) : "memory");
}
__device__ __forceinline__ float tanh_fast(float x) {
    float y;
    asm("tanh.approx.f32 %0, %1;" : "=f"(y) : "f"(x));
    return y;
}
__device__ __forceinline__ float sigmoid_fast(float x) {
    return 0.5f * tanh_fast(0.5f * x) + 0.5f;
}

// Single-hop grid barrier (proven R9/R11/R13); monotonic targets.
__device__ __forceinline__ void grid_barrier(unsigned target) {
    __syncthreads();
    int tid = threadIdx.x;
    if (tid == 0) st_rel(&g_flags[blockIdx.x * 8], target);
    if (tid < NBLK) {
        while (ld_acq(&g_flags[tid * 8]) < target) { }
    }
    __syncthreads();
}

__global__ void split_fp16_kernel(const float* __restrict__ src,
                                  half* __restrict__ hi, half* __restrict__ lo, int n) {
    int i4 = (blockIdx.x * 256 + threadIdx.x) * 4;
    if (i4 >= n) return;
    float4 v = *(const float4*)(src + i4);
    half h0 = __float2half(v.x), h1 = __float2half(v.y);
    half h2 = __float2half(v.z), h3 = __float2half(v.w);
    hi[i4+0]=h0; hi[i4+1]=h1; hi[i4+2]=h2; hi[i4+3]=h3;
    lo[i4+0]=__float2half(v.x-__half2float(h0));
    lo[i4+1]=__float2half(v.y-__half2float(h1));
    lo[i4+2]=__float2half(v.z-__half2float(h2));
    lo[i4+3]=__float2half(v.w-__half2float(h3));
}

// ---------------------------------------------------------------------------
// Layer-0 input GEMM (K=64): xg[jb][m][g*8+jl] = A@W^T + b1 + b2  (R11 verbatim)
// ---------------------------------------------------------------------------
__global__ void __launch_bounds__(256)
hgemm_split_kernel(const half* __restrict__ Ahi, const half* __restrict__ Alo,
                   const half* __restrict__ Whi, const half* __restrict__ Wlo,
                   const float* __restrict__ b1, const float* __restrict__ b2,
                   float* __restrict__ C, int M, int K) {
    __shared__ half sA[2][2][64 * 40];
    __shared__ half sB[2][2][64 * 40];
    const int tid = threadIdx.x, lane = tid & 31, w = tid >> 5;
    const int mi = w & 1, ni = w >> 1;
    const int r = lane >> 2, q = lane & 3;
    const int m0 = blockIdx.y * 64, n0 = blockIdx.x * 64;
    const int srow = tid >> 2, skq = (tid & 3) * 8;

    float acc[2][2][4];
#pragma unroll
    for (int a = 0; a < 2; a++)
#pragma unroll
        for (int b = 0; b < 2; b++)
#pragma unroll
            for (int c = 0; c < 4; c++) acc[a][b][c] = 0.f;

    const int NIT = K / 32;
    cp16(&sA[0][0][srow*40+skq], Ahi + (size_t)(m0+srow)*K + skq);
    cp16(&sA[0][1][srow*40+skq], Alo + (size_t)(m0+srow)*K + skq);
    cp16(&sB[0][0][srow*40+skq], Whi + (size_t)(n0+srow)*K + skq);
    cp16(&sB[0][1][srow*40+skq], Wlo + (size_t)(n0+srow)*K + skq);
    CP_COMMIT();

    for (int it = 0; it < NIT; it++) {
        CP_WAIT0();
        __syncthreads();
        if (it + 1 < NIT) {
            int k0 = (it+1)*32, bf = (it+1) & 1;
            cp16(&sA[bf][0][srow*40+skq], Ahi + (size_t)(m0+srow)*K + k0 + skq);
            cp16(&sA[bf][1][srow*40+skq], Alo + (size_t)(m0+srow)*K + k0 + skq);
            cp16(&sB[bf][0][srow*40+skq], Whi + (size_t)(n0+srow)*K + k0 + skq);
            cp16(&sB[bf][1][srow*40+skq], Wlo + (size_t)(n0+srow)*K + k0 + skq);
            CP_COMMIT();
        }
        const half *Abh = sA[it&1][0], *Abl = sA[it&1][1];
        const half *Bbh = sB[it&1][0], *Bbl = sB[it&1][1];
#pragma unroll
        for (int s = 0; s < 2; s++) {
            const int kb = s * 16;
            uint32_t Ah[2][4], Al[2][4], Bh[2][2], Bl[2][2];
#pragma unroll
            for (int mt = 0; mt < 2; mt++) {
                ldsm4(Ah[mt], Abh + (mi*32 + mt*16 + (lane&15))*40 + kb + ((lane>>4)<<3));
                ldsm4(Al[mt], Abl + (mi*32 + mt*16 + (lane&15))*40 + kb + ((lane>>4)<<3));
            }
#pragma unroll
            for (int nt = 0; nt < 2; nt++) {
                ldsm2(Bh[nt], Bbh + (ni*16 + nt*8 + (lane&7))*40 + kb + (((lane>>3)&1)<<3));
                ldsm2(Bl[nt], Bbl + (ni*16 + nt*8 + (lane&7))*40 + kb + (((lane>>3)&1)<<3));
            }
#pragma unroll
            for (int mt = 0; mt < 2; mt++)
#pragma unroll
                for (int nt = 0; nt < 2; nt++) {
                    mma16816(acc[mt][nt], Ah[mt], Bh[nt]);
                    mma16816(acc[mt][nt], Ah[mt], Bl[nt]);
                    mma16816(acc[mt][nt], Al[mt], Bh[nt]);
                }
        }
        __syncthreads();
    }
#pragma unroll
    for (int mt = 0; mt < 2; mt++)
#pragma unroll
        for (int nt = 0; nt < 2; nt++) {
            int row = m0 + mi*32 + mt*16 + r;
            int col = n0 + ni*16 + nt*8 + q*2;
            int g = col >> 10, rem = col & 1023, jb = rem >> 3, jl = rem & 7;
            float bs0 = b1[col] + b2[col], bs1 = b1[col+1] + b2[col+1];
            size_t base = (size_t)jb * ((size_t)SEQ * BATCH * 32) + (size_t)row * 32 + g*8 + jl;
            *(float2*)(C + base) = make_float2(acc[mt][nt][0]+bs0, acc[mt][nt][1]+bs1);
            *(float2*)(C + base + 8*32) = make_float2(acc[mt][nt][2]+bs0, acc[mt][nt][3]+bs1);
        }
}

// ---------------------------------------------------------------------------
// Fused 2-layer persistent recurrence. Block bx owns 8 j-cols (both layers).
// Warps: mt = w&3, ki = w>>2 (K half).
// smem: W0|W1a|W1b (3x66048) | psum 17408 | xg 2x8192 | mbar 16 = 231952 B
// ---------------------------------------------------------------------------
#define WSS 1032
#define WB_HALFS (32 * WSS)
#define PS_OFF  (3 * WB_HALFS * 2)      // 198144
#define XG_OFF  (PS_OFF + 17408)        // 215552
#define MB_OFF  (XG_OFF + 16384)        // 231936
#define SMEM_TOT (MB_OFF + 16)          // 231952
#define XG_B    8192u

__device__ __forceinline__ void load_wbank(const float* __restrict__ W, half* dst,
                                           int j0, int tid) {
    for (int idx = tid; idx < 32 * 256; idx += NTHR) {
        int n = idx >> 8, kq = (idx & 255) * 4;
        int grow = (n >> 3) * HID + j0 + (n & 7);
        float4 v = *(const float4*)(W + (size_t)grow * HID + kq);
        half* ph = dst + n * WSS + kq;
        ph[0]=__float2half(v.x); ph[1]=__float2half(v.y);
        ph[2]=__float2half(v.z); ph[3]=__float2half(v.w);
    }
}

// One K=512 half-matmul: A frags streamed from GMEM, B from smem bank.
// acc accumulated (not zeroed).
__device__ __forceinline__ void mm_k512(const half* hb, const half* wb,
                                        int lrow, int lcol, float acc[4][4]) {
    uint32_t abuf[8][4];
#pragma unroll
    for (int i = 0; i < 8; i++) {
        uint4 v = *(const uint4*)(hb + i * 256);
        abuf[i][0]=v.x; abuf[i][1]=v.y; abuf[i][2]=v.z; abuf[i][3]=v.w;
    }
    uint32_t B0[4][4], B1[4][4];
#pragma unroll
    for (int nt = 0; nt < 4; nt++)
        ldsm4(B0[nt], wb + (nt*8 + lrow)*WSS + lcol);
#pragma unroll
    for (int u = 0; u < 16; u++) {
        uint32_t (*Bc)[4] = (u & 1) ? B1 : B0;
        uint32_t (*Bn)[4] = (u & 1) ? B0 : B1;
        if (u < 15) {
            const int kg = (u+1)*32;
#pragma unroll
            for (int nt = 0; nt < 4; nt++)
                ldsm4(Bn[nt], wb + (nt*8 + lrow)*WSS + kg + lcol);
        }
        const int i0 = (2*u) & 7, i1 = (2*u+1) & 7;
#pragma unroll
        for (int nt = 0; nt < 4; nt++) {
            mma16816(acc[nt], abuf[i0], Bc[nt]);
            mma16816(acc[nt], abuf[i1], Bc[nt]+2);
        }
        if (2*u + 8 < 32) {
            uint4 v0 = *(const uint4*)(hb + (2*u+8) * 256);
            abuf[i0][0]=v0.x; abuf[i0][1]=v0.y; abuf[i0][2]=v0.z; abuf[i0][3]=v0.w;
            uint4 v1 = *(const uint4*)(hb + (2*u+9) * 256);
            abuf[i1][0]=v1.x; abuf[i1][1]=v1.y; abuf[i1][2]=v1.z; abuf[i1][3]=v1.w;
        }
    }
}

__global__ void __launch_bounds__(NTHR, 1)
lstm_fused(const float* __restrict__ xg,      // [jb][t*64+b][32] layer-0 gates
           const float* __restrict__ Whh0,
           const float* __restrict__ Wih1,
           const float* __restrict__ Whh1,
           const float* __restrict__ bih1,
           const float* __restrict__ bhh1,
           half* __restrict__ h1f, half* __restrict__ h2f,
           float* __restrict__ hseq)          // [t][b][1024] fp32 (h2)
{
    extern __shared__ char smem[];
    half*  wsh0  = (half*)smem;
    half*  wsh1a = wsh0 + WB_HALFS;
    half*  wsh1b = wsh1a + WB_HALFS;
    float* psum  = (float*)(smem + PS_OFF);
    float* xgs   = (float*)(smem + XG_OFF);
    uint64_t* xmb = (uint64_t*)(smem + MB_OFF);

    const int tid = threadIdx.x, lane = tid & 31, w = tid >> 5;
    const int mt = w & 3, ki = w >> 2;
    const int bx = blockIdx.x;
    const int j0 = bx * 8;
    const float* xgb = xg + (size_t)bx * ((size_t)SEQ * BATCH * 32);

    if (tid == 0) { mbar_init(&xmb[0], 1); mbar_init(&xmb[1], 1); }

    load_wbank(Whh0, wsh0,  j0, tid);
    load_wbank(Wih1, wsh1a, j0, tid);
    load_wbank(Whh1, wsh1b, j0, tid);
    __syncthreads();

    if (tid == 0) {    // prologue: xg(0)
        mbar_expect(&xmb[0], XG_B);
        cpbulk(xgs, xgb, XG_B, &xmb[0]);
    }

    unsigned xph[2] = {0u, 0u};
    const int pfm = tid >> 5, pl = tid & 31;
    const int pbr = pfm * 16 + (pl >> 2), pjp = (pl & 3) * 2;
    float creg0[4] = {0.f, 0.f, 0.f, 0.f};
    float creg1[4] = {0.f, 0.f, 0.f, 0.f};
    const int lrow = lane & 7, lcol = ((lane >> 3) & 3) * 8;
    const size_t warp_off = ((size_t)mt * 64 + ki * 32) * 256 + lane * 8;
    const int prow = mt*16 + (lane>>2), pcol = (lane&3)*2;

    // layer-1 biases for this thread's 8 gate values
    float bi1[4][2];
#pragma unroll
    for (int g = 0; g < 4; g++)
#pragma unroll
        for (int d = 0; d < 2; d++) {
            int idx = g * HID + j0 + pjp + d;
            bi1[g][d] = bih1[idx] + bhh1[idx];
        }

    for (int s = 0; s <= SEQ; s++) {
        if (tid == 0 && s + 1 < SEQ) {
            mbar_expect(&xmb[(s+1)&1], XG_B);
            cpbulk((char*)xgs + ((s+1)&1) * XG_B, xgb + (size_t)(s+1) * 2048, XG_B, &xmb[(s+1)&1]);
        }

        // ---- layer-0 matmul: gates0(s) partial = h1(s-1) @ Whh0 ----
        if (s > 0 && s < SEQ) {
            const half* hb = h1f + (size_t)(s-1) * 65536 + warp_off;
            float acc[4][4];
#pragma unroll
            for (int nt = 0; nt < 4; nt++)
#pragma unroll
                for (int c = 0; c < 4; c++) acc[nt][c] = 0.f;
            mm_k512(hb, wsh0 + ki*512, lrow, lcol, acc);
#pragma unroll
            for (int nt = 0; nt < 4; nt++) {
                *(float2*)(psum + ((ki*64 + prow)*34) + nt*8 + pcol) =
                    make_float2(acc[nt][0], acc[nt][1]);
                *(float2*)(psum + ((ki*64 + prow + 8)*34) + nt*8 + pcol) =
                    make_float2(acc[nt][2], acc[nt][3]);
            }
        }
        __syncthreads();

        // ---- layer-0 pointwise: h1(s) ----
        if (s < SEQ) {
            mbar_wait(&xmb[s&1], xph[s&1]); xph[s&1] ^= 1u;
            if (tid < 128) {
                const float* xt = xgs + (s&1) * 2048;
                float gate[4][4];
#pragma unroll
                for (int g = 0; g < 4; g++)
#pragma unroll
                    for (int rb = 0; rb < 2; rb++) {
                        int b = pbr + rb * 8;
                        float2 xv = *(const float2*)(xt + b * 32 + g * 8 + pjp);
                        float v0 = xv.x, v1 = xv.y;
                        if (s > 0) {
                            float2 pa = *(const float2*)(psum + b * 34 + g * 8 + pjp);
                            float2 pb = *(const float2*)(psum + (64 + b) * 34 + g * 8 + pjp);
                            v0 += pa.x + pb.x;
                            v1 += pa.y + pb.y;
                        }
                        gate[g][rb*2+0] = v0;
                        gate[g][rb*2+1] = v1;
                    }
                half hh[4];
#pragma unroll
                for (int e = 0; e < 4; e++) {
                    float ig = sigmoid_fast(gate[0][e]);
                    float fg = sigmoid_fast(gate[1][e]);
                    float gg = tanh_fast(gate[2][e]);
                    float og = sigmoid_fast(gate[3][e]);
                    float cn = fmaf(fg, creg0[e], ig * gg);
                    creg0[e] = cn;
                    hh[e] = __float2half(og * tanh_fast(cn));
                }
                half2 p0 = __halves2half2(hh[0], hh[1]);
                half2 p1 = __halves2half2(hh[2], hh[3]);
                uint2 u2 = make_uint2(*(unsigned*)&p0, *(unsigned*)&p1);
                size_t o = (size_t)s * 65536 + ((size_t)pfm * 64 + (bx >> 1)) * 256
                           + pl * 8 + (bx & 1) * 4;
                *(uint2*)(h1f + o) = u2;
            }
        }
        __syncthreads();   // psum free; pw0 done

        // ---- layer-1 matmul: gates1(s-1) = h1(s-1)@Wih1 + h2(s-2)@Whh1 ----
        if (s >= 1) {
            float acc[4][4];
#pragma unroll
            for (int nt = 0; nt < 4; nt++)
#pragma unroll
                for (int c = 0; c < 4; c++) acc[nt][c] = 0.f;
            const half* hb1 = h1f + (size_t)(s-1) * 65536 + warp_off;
            mm_k512(hb1, wsh1a + ki*512, lrow, lcol, acc);
            if (s >= 2) {
                const half* hb2 = h2f + (size_t)(s-2) * 65536 + warp_off;
                mm_k512(hb2, wsh1b + ki*512, lrow, lcol, acc);
            }
#pragma unroll
            for (int nt = 0; nt < 4; nt++) {
                *(float2*)(psum + ((ki*64 + prow)*34) + nt*8 + pcol) =
                    make_float2(acc[nt][0], acc[nt][1]);
                *(float2*)(psum + ((ki*64 + prow + 8)*34) + nt*8 + pcol) =
                    make_float2(acc[nt][2], acc[nt][3]);
            }
        }
        __syncthreads();

        // ---- layer-1 pointwise: h2(s-1) + fp32 output ----
        if (s >= 1 && tid < 128) {
            const int t1 = s - 1;
            float gate[4][4];
#pragma unroll
            for (int g = 0; g < 4; g++)
#pragma unroll
                for (int rb = 0; rb < 2; rb++) {
                    int b = pbr + rb * 8;
                    float2 pa = *(const float2*)(psum + b * 34 + g * 8 + pjp);
                    float2 pb = *(const float2*)(psum + (64 + b) * 34 + g * 8 + pjp);
                    gate[g][rb*2+0] = pa.x + pb.x + bi1[g][0];
                    gate[g][rb*2+1] = pa.y + pb.y + bi1[g][1];
                }
            half hh[4];
            float hv[4];
#pragma unroll
            for (int e = 0; e < 4; e++) {
                float ig = sigmoid_fast(gate[0][e]);
                float fg = sigmoid_fast(gate[1][e]);
                float gg = tanh_fast(gate[2][e]);
                float og = sigmoid_fast(gate[3][e]);
                float cn = fmaf(fg, creg1[e], ig * gg);
                creg1[e] = cn;
                hv[e] = og * tanh_fast(cn);
                hh[e] = __float2half(hv[e]);
            }
            float* h_out = hseq + (size_t)t1 * BATCH * HID;
            *(float2*)(h_out + (size_t)pbr * HID + j0 + pjp) = make_float2(hv[0], hv[1]);
            *(float2*)(h_out + (size_t)(pbr + 8) * HID + j0 + pjp) = make_float2(hv[2], hv[3]);
            half2 p0 = __halves2half2(hh[0], hh[1]);
            half2 p1 = __halves2half2(hh[2], hh[3]);
            uint2 u2 = make_uint2(*(unsigned*)&p0, *(unsigned*)&p1);
            size_t o = (size_t)t1 * 65536 + ((size_t)pfm * 64 + (bx >> 1)) * 256
                       + pl * 8 + (bx & 1) * 4;
            *(uint2*)(h2f + o) = u2;
        }

        grid_barrier((unsigned)(s + 1));
    }

    // end-of-kernel reset (last block resets flags)
    __syncthreads();
    if (tid == 0) {
        unsigned c = atomicAdd(&g_done, 1u);
        if (c == NBLK - 1u) {
            for (int i = 0; i < NBLK; i++) g_flags[i * 8] = 0u;
            __threadfence();
            g_done = 0u;
        }
        mbar_inval(&xmb[0]); mbar_inval(&xmb[1]);
    }
}

// ---------------------------------------------------------------------------
__global__ void final_linear_kernel(const float* __restrict__ h_last,
                                    const float* __restrict__ Wl,
                                    const float* __restrict__ bl,
                                    float* __restrict__ y) {
    int b = blockIdx.x;
    __shared__ float red[128];
    float s = 0.f;
    for (int k = threadIdx.x; k < HID; k += 128)
        s += h_last[(size_t)b * HID + k] * Wl[k];
    red[threadIdx.x] = s;
    __syncthreads();
    for (int off = 64; off > 0; off >>= 1) {
        if (threadIdx.x < off) red[threadIdx.x] += red[threadIdx.x + off];
        __syncthreads();
    }
    if (threadIdx.x == 0) y[b] = red[0] + bl[0];
}

// ---------------------------------------------------------------------------
extern "C" void kernel_launch(void* const* d_in, const int* in_sizes, int n_in,
                              void* d_out, int out_size) {
    (void)in_sizes; (void)n_in; (void)out_size;
    const float* x    = (const float*)d_in[0];
    const float* Wih0 = (const float*)d_in[1];
    const float* Whh0 = (const float*)d_in[2];
    const float* bih0 = (const float*)d_in[3];
    const float* bhh0 = (const float*)d_in[4];
    const float* Wih1 = (const float*)d_in[5];
    const float* Whh1 = (const float*)d_in[6];
    const float* bih1 = (const float*)d_in[7];
    const float* bhh1 = (const float*)d_in[8];
    const float* Wlin = (const float*)d_in[9];
    const float* blin = (const float*)d_in[10];

    float* out      = (float*)d_out;
    float* lstm_out = out;
    float* ypred    = out + (size_t)SEQ * BATCH * HID;

    float *xg; half *h1f, *h2f, *whi, *wlo, *xhi, *xlo;
    cudaGetSymbolAddress((void**)&xg,  g_xg);
    cudaGetSymbolAddress((void**)&h1f, g_h1f);
    cudaGetSymbolAddress((void**)&h2f, g_h2f);
    cudaGetSymbolAddress((void**)&whi, g_w_hi);
    cudaGetSymbolAddress((void**)&wlo, g_w_lo);
    cudaGetSymbolAddress((void**)&xhi, g_x_hi);
    cudaGetSymbolAddress((void**)&xlo, g_x_lo);

    cudaFuncSetAttribute(lstm_fused,
                         cudaFuncAttributeMaxDynamicSharedMemorySize, SMEM_TOT);

    const int M = SEQ * BATCH;
    dim3 gg(G4 / 64, M / 64);

    // Layer-0 input GEMM
    int nx = SEQ * BATCH * INP;
    split_fp16_kernel<<<nx/4/256, 256>>>(x, xhi, xlo, nx);
    int nw0 = G4 * INP;
    split_fp16_kernel<<<nw0/4/256, 256>>>(Wih0, whi, wlo, nw0);
    hgemm_split_kernel<<<gg, 256>>>(xhi, xlo, whi, wlo, bih0, bhh0, xg, M, INP);

    // Fused 2-layer recurrence
    lstm_fused<<<NBLK, NTHR, SMEM_TOT>>>(xg, Whh0, Wih1, Whh1, bih1, bhh1,
                                         h1f, h2f, lstm_out);

    // Head
    final_linear_kernel<<<BATCH, 128>>>(lstm_out + (size_t)(SEQ-1) * BATCH * HID,
                                        Wlin, blin, ypred);
}